// round 1
// baseline (speedup 1.0000x reference)
#include <cuda_runtime.h>
#include <cuda_bf16.h>
#include <math.h>

// Problem constants
#define BATCH 4
#define SEQ 2048
#define DMODEL 1024
#define NHEADS 16
#define DK 64
#define MTOT (BATCH * SEQ)            // 8192

// Scratch (module-load allocated, not runtime alloc)
__device__ float g_qkv[(size_t)MTOT * 3 * DMODEL];   // [8192, 3072]
__device__ float g_attn[(size_t)MTOT * DMODEL];      // [8192, 1024]

// ---------------------------------------------------------------------------
// SGEMM: C[M,N] = A[M,K] * B[N,K]^T   (both row-major, K contiguous)
// 128x128 tile, BK=16, 256 threads, 8x8 microtile.
// ---------------------------------------------------------------------------
__global__ __launch_bounds__(256, 2)
void sgemm_nt(const float* __restrict__ A, const float* __restrict__ B,
              float* __restrict__ C, int M, int N, int K) {
    const int BM = 128, BN = 128, BKT = 16;
    __shared__ float As[BKT][BM + 4];
    __shared__ float Bs[BKT][BN + 4];

    const int tx = threadIdx.x & 15;
    const int ty = threadIdx.x >> 4;
    const int row0 = blockIdx.y * BM;
    const int col0 = blockIdx.x * BN;

    float acc[8][8];
#pragma unroll
    for (int i = 0; i < 8; i++)
#pragma unroll
        for (int j = 0; j < 8; j++) acc[i][j] = 0.f;

    for (int k0 = 0; k0 < K; k0 += BKT) {
        // Load A tile (128 x 16) transposed into As[k][m]
#pragma unroll
        for (int i = 0; i < 2; i++) {
            int lin = threadIdx.x + i * 256;           // 0..511
            int r = lin >> 2;                          // 0..127
            int c = (lin & 3) * 4;                     // 0,4,8,12
            float4 v = *(const float4*)&A[(size_t)(row0 + r) * K + k0 + c];
            As[c + 0][r] = v.x; As[c + 1][r] = v.y;
            As[c + 2][r] = v.z; As[c + 3][r] = v.w;
        }
        // Load B tile (128 x 16) transposed into Bs[k][n]
#pragma unroll
        for (int i = 0; i < 2; i++) {
            int lin = threadIdx.x + i * 256;
            int r = lin >> 2;
            int c = (lin & 3) * 4;
            float4 v = *(const float4*)&B[(size_t)(col0 + r) * K + k0 + c];
            Bs[c + 0][r] = v.x; Bs[c + 1][r] = v.y;
            Bs[c + 2][r] = v.z; Bs[c + 3][r] = v.w;
        }
        __syncthreads();

#pragma unroll
        for (int k = 0; k < BKT; k++) {
            float4 a0 = *(const float4*)&As[k][8 * ty];
            float4 a1 = *(const float4*)&As[k][8 * ty + 4];
            float4 b0 = *(const float4*)&Bs[k][8 * tx];
            float4 b1 = *(const float4*)&Bs[k][8 * tx + 4];
            float a[8] = {a0.x, a0.y, a0.z, a0.w, a1.x, a1.y, a1.z, a1.w};
            float b[8] = {b0.x, b0.y, b0.z, b0.w, b1.x, b1.y, b1.z, b1.w};
#pragma unroll
            for (int i = 0; i < 8; i++)
#pragma unroll
                for (int j = 0; j < 8; j++) acc[i][j] += a[i] * b[j];
        }
        __syncthreads();
    }

    // Write C
#pragma unroll
    for (int i = 0; i < 8; i++) {
        float* crow = &C[(size_t)(row0 + 8 * ty + i) * N + col0 + 8 * tx];
        *(float4*)&crow[0] = make_float4(acc[i][0], acc[i][1], acc[i][2], acc[i][3]);
        *(float4*)&crow[4] = make_float4(acc[i][4], acc[i][5], acc[i][6], acc[i][7]);
    }
}

// ---------------------------------------------------------------------------
// RoPE in-place on q and k slices of g_qkv.
// One thread per (token, head, pair) — handles both q and k.
// ---------------------------------------------------------------------------
__global__ void rope_kernel(float* __restrict__ qkv, const int* __restrict__ pos) {
    int idx = blockIdx.x * blockDim.x + threadIdx.x;
    if (idx >= MTOT * NHEADS * (DK / 2)) return;
    int m = idx >> 9;            // / (16*32)
    int r = idx & 511;
    int h = r >> 5;
    int i = r & 31;              // pair index

    float p = (float)pos[m];
    // inv_freq = theta^(-2i/64)
    float inv = expf(-logf(10000.0f) * (2.0f * (float)i) / 64.0f);
    float ang = p * inv;
    float sn, cs;
    sincosf(ang, &sn, &cs);

    float* q = qkv + (size_t)m * 3072 + h * DK + 2 * i;
    float* k = q + DMODEL;
    float q1 = q[0], q2 = q[1];
    q[0] = q1 * cs - q2 * sn;
    q[1] = q1 * sn + q2 * cs;
    float k1 = k[0], k2 = k[1];
    k[0] = k1 * cs - k2 * sn;
    k[1] = k1 * sn + k2 * cs;
}

// ---------------------------------------------------------------------------
// Causal flash attention, fp32 SIMT.
// Block: 256 threads, BQ=64 query rows, iterate BK=64 key tiles.
// Online softmax; O accumulators in registers (4x4 microtile per thread).
// ---------------------------------------------------------------------------
#define BQ 64
#define BKEY 64
#define SPITCH 68

__global__ __launch_bounds__(256, 2)
void flash_kernel(const float* __restrict__ qkv, float* __restrict__ out) {
    extern __shared__ float sm[];
    float* Qs = sm;                        // [BQ][SPITCH]   (pre-scaled Q)
    float* Kt = Qs + BQ * SPITCH;          // [DK][SPITCH]   K transposed: Kt[d][j]
    float* Vs = Kt + DK * SPITCH;          // [BKEY][SPITCH]
    float* Ss = Vs + BKEY * SPITCH;        // [BQ][SPITCH]   scores -> probs
    __shared__ float m_s[BQ], l_s[BQ], alpha_s[BQ];

    const int qt = blockIdx.x;
    const int h  = blockIdx.y;
    const int b  = blockIdx.z;
    const int q0 = qt * BQ;
    const int tid = threadIdx.x;
    const int tx = tid & 15, ty = tid >> 4;
    const float scale = 0.125f;  // 1/sqrt(64)

    const float* base = qkv + (size_t)b * SEQ * 3072 + h * DK;

    // Load Q tile (pre-scaled)
#pragma unroll
    for (int i = 0; i < 4; i++) {
        int lin = tid + i * 256;          // 0..1023
        int r = lin >> 4;
        int c = (lin & 15) * 4;
        float4 v = *(const float4*)&base[(size_t)(q0 + r) * 3072 + c];
        float* dst = &Qs[r * SPITCH + c];
        dst[0] = v.x * scale; dst[1] = v.y * scale;
        dst[2] = v.z * scale; dst[3] = v.w * scale;
    }
    if (tid < BQ) { m_s[tid] = -1e30f; l_s[tid] = 0.f; }

    float o[4][4];
#pragma unroll
    for (int i = 0; i < 4; i++)
#pragma unroll
        for (int j = 0; j < 4; j++) o[i][j] = 0.f;

    const int ktiles = qt + 1;
    for (int kt = 0; kt < ktiles; kt++) {
        const int k0 = kt * BKEY;
        __syncthreads();   // protect Kt/Vs/Ss from previous iteration's readers

        // Load K (transposed) and V tiles
#pragma unroll
        for (int i = 0; i < 4; i++) {
            int lin = tid + i * 256;
            int r = lin >> 4;
            int c = (lin & 15) * 4;
            const float* kp = &base[(size_t)(k0 + r) * 3072 + DMODEL + c];
            float4 kv = *(const float4*)kp;
            Kt[(c + 0) * SPITCH + r] = kv.x;
            Kt[(c + 1) * SPITCH + r] = kv.y;
            Kt[(c + 2) * SPITCH + r] = kv.z;
            Kt[(c + 3) * SPITCH + r] = kv.w;
            float4 vv = *(const float4*)(kp + DMODEL);
            *(float4*)&Vs[r * SPITCH + c] = vv;
        }
        __syncthreads();

        // Phase A: S = Qs @ K^T  (4x4 microtile per thread)
        float s[4][4];
#pragma unroll
        for (int i = 0; i < 4; i++)
#pragma unroll
            for (int j = 0; j < 4; j++) s[i][j] = 0.f;
#pragma unroll
        for (int d = 0; d < DK; d++) {
            float a0 = Qs[(4 * ty + 0) * SPITCH + d];
            float a1 = Qs[(4 * ty + 1) * SPITCH + d];
            float a2 = Qs[(4 * ty + 2) * SPITCH + d];
            float a3 = Qs[(4 * ty + 3) * SPITCH + d];
            float4 bb = *(const float4*)&Kt[d * SPITCH + 4 * tx];
            s[0][0] += a0 * bb.x; s[0][1] += a0 * bb.y; s[0][2] += a0 * bb.z; s[0][3] += a0 * bb.w;
            s[1][0] += a1 * bb.x; s[1][1] += a1 * bb.y; s[1][2] += a1 * bb.z; s[1][3] += a1 * bb.w;
            s[2][0] += a2 * bb.x; s[2][1] += a2 * bb.y; s[2][2] += a2 * bb.z; s[2][3] += a2 * bb.w;
            s[3][0] += a3 * bb.x; s[3][1] += a3 * bb.y; s[3][2] += a3 * bb.z; s[3][3] += a3 * bb.w;
        }
#pragma unroll
        for (int i = 0; i < 4; i++)
            *(float4*)&Ss[(4 * ty + i) * SPITCH + 4 * tx] =
                make_float4(s[i][0], s[i][1], s[i][2], s[i][3]);
        __syncthreads();

        // Phase B: online softmax per row (threads 0..63)
        if (tid < BQ) {
            int grow = q0 + tid;
            int nvalid = grow - k0 + 1;
            if (nvalid > BKEY) nvalid = BKEY;
            float mo = m_s[tid];
            float mn = mo;
            float* srow = &Ss[tid * SPITCH];
            for (int j = 0; j < nvalid; j++) mn = fmaxf(mn, srow[j]);
            float alpha = __expf(mo - mn);
            float lsum = 0.f;
#pragma unroll 8
            for (int j = 0; j < BKEY; j++) {
                float p = (j < nvalid) ? __expf(srow[j] - mn) : 0.f;
                srow[j] = p;
                lsum += p;
            }
            m_s[tid] = mn;
            l_s[tid] = l_s[tid] * alpha + lsum;
            alpha_s[tid] = alpha;
        }
        __syncthreads();

        // Phase C: O = O*alpha + P @ V
        float al0 = alpha_s[4 * ty + 0];
        float al1 = alpha_s[4 * ty + 1];
        float al2 = alpha_s[4 * ty + 2];
        float al3 = alpha_s[4 * ty + 3];
#pragma unroll
        for (int j = 0; j < 4; j++) {
            o[0][j] *= al0; o[1][j] *= al1; o[2][j] *= al2; o[3][j] *= al3;
        }
#pragma unroll
        for (int kj = 0; kj < BKEY; kj++) {
            float p0 = Ss[(4 * ty + 0) * SPITCH + kj];
            float p1 = Ss[(4 * ty + 1) * SPITCH + kj];
            float p2 = Ss[(4 * ty + 2) * SPITCH + kj];
            float p3 = Ss[(4 * ty + 3) * SPITCH + kj];
            float4 vv = *(const float4*)&Vs[kj * SPITCH + 4 * tx];
            o[0][0] += p0 * vv.x; o[0][1] += p0 * vv.y; o[0][2] += p0 * vv.z; o[0][3] += p0 * vv.w;
            o[1][0] += p1 * vv.x; o[1][1] += p1 * vv.y; o[1][2] += p1 * vv.z; o[1][3] += p1 * vv.w;
            o[2][0] += p2 * vv.x; o[2][1] += p2 * vv.y; o[2][2] += p2 * vv.z; o[2][3] += p2 * vv.w;
            o[3][0] += p3 * vv.x; o[3][1] += p3 * vv.y; o[3][2] += p3 * vv.z; o[3][3] += p3 * vv.w;
        }
    }

    // Epilogue: divide by l, write to g_attn in (b, s, h*64+d) layout
    float li0 = 1.f / l_s[4 * ty + 0];
    float li1 = 1.f / l_s[4 * ty + 1];
    float li2 = 1.f / l_s[4 * ty + 2];
    float li3 = 1.f / l_s[4 * ty + 3];
    float* op = out + ((size_t)(b * SEQ + q0)) * DMODEL + h * DK;
    *(float4*)&op[(4 * ty + 0) * DMODEL + 4 * tx] =
        make_float4(o[0][0] * li0, o[0][1] * li0, o[0][2] * li0, o[0][3] * li0);
    *(float4*)&op[(4 * ty + 1) * DMODEL + 4 * tx] =
        make_float4(o[1][0] * li1, o[1][1] * li1, o[1][2] * li1, o[1][3] * li1);
    *(float4*)&op[(4 * ty + 2) * DMODEL + 4 * tx] =
        make_float4(o[2][0] * li2, o[2][1] * li2, o[2][2] * li2, o[2][3] * li2);
    *(float4*)&op[(4 * ty + 3) * DMODEL + 4 * tx] =
        make_float4(o[3][0] * li3, o[3][1] * li3, o[3][2] * li3, o[3][3] * li3);
}

// ---------------------------------------------------------------------------
// Launch
// ---------------------------------------------------------------------------
extern "C" void kernel_launch(void* const* d_in, const int* in_sizes, int n_in,
                              void* d_out, int out_size) {
    const float* x     = (const float*)d_in[0];
    const int*   pos   = (const int*)d_in[1];
    const float* w_qkv = (const float*)d_in[2];
    const float* w_o   = (const float*)d_in[3];
    float* out = (float*)d_out;

    float* qkv = nullptr;
    float* attn = nullptr;
    cudaGetSymbolAddress((void**)&qkv, g_qkv);
    cudaGetSymbolAddress((void**)&attn, g_attn);

    // 1) QKV projection: [8192,3072] = x[8192,1024] @ w_qkv[3072,1024]^T
    sgemm_nt<<<dim3(3 * DMODEL / 128, MTOT / 128), 256>>>(x, w_qkv, qkv,
                                                          MTOT, 3 * DMODEL, DMODEL);

    // 2) RoPE on q,k
    {
        int total = MTOT * NHEADS * (DK / 2);
        rope_kernel<<<(total + 255) / 256, 256>>>(qkv, pos);
    }

    // 3) Causal flash attention
    {
        size_t smem = (size_t)4 * 64 * SPITCH * sizeof(float);  // 69632 B
        cudaFuncSetAttribute(flash_kernel,
                             cudaFuncAttributeMaxDynamicSharedMemorySize, (int)smem);
        flash_kernel<<<dim3(SEQ / BQ, NHEADS, BATCH), 256, smem>>>(qkv, attn);
    }

    // 4) Output projection: [8192,1024] = attn[8192,1024] @ w_o[1024,1024]^T
    sgemm_nt<<<dim3(DMODEL / 128, MTOT / 128), 256>>>(attn, w_o, out,
                                                      MTOT, DMODEL, DMODEL);
}

// round 2
// speedup vs baseline: 3.6576x; 3.6576x over previous
#include <cuda_runtime.h>
#include <math.h>

#define BATCH 4
#define SEQ 2048
#define DMODEL 1024
#define NHEADS 16
#define DK 64
#define MTOT (BATCH * SEQ)   // 8192

// Scratch (module-load allocated)
__device__ float g_qkv[(size_t)MTOT * 3 * DMODEL];   // [8192, 3072]
__device__ float g_attn[(size_t)MTOT * DMODEL];      // [8192, 1024]

// ---------------------------------------------------------------------------
// tf32 helpers
// ---------------------------------------------------------------------------
__device__ __forceinline__ unsigned f2tf(float f) {
    unsigned r;
    asm("cvt.rna.tf32.f32 %0, %1;" : "=r"(r) : "f"(f));
    return r;
}

__device__ __forceinline__ void mma8(float* c, const unsigned* a, const unsigned* b) {
    asm volatile(
        "mma.sync.aligned.m16n8k8.row.col.f32.tf32.tf32.f32 "
        "{%0,%1,%2,%3},{%4,%5,%6,%7},{%8,%9},{%0,%1,%2,%3};"
        : "+f"(c[0]), "+f"(c[1]), "+f"(c[2]), "+f"(c[3])
        : "r"(a[0]), "r"(a[1]), "r"(a[2]), "r"(a[3]), "r"(b[0]), "r"(b[1]));
}

// ---------------------------------------------------------------------------
// GEMM C[M,N] = A[M,K] * B[N,K]^T  via tf32 tensor cores.
// Block 128x128, BK=32, 256 threads (8 warps, 4x2), warp tile 32x64.
// Smem stored k-major with pitch 136 (bank-conflict-free fragment loads).
// ---------------------------------------------------------------------------
#define GPITCH 136

__global__ __launch_bounds__(256, 2)
void gemm_tf32(const float* __restrict__ A, const float* __restrict__ B,
               float* __restrict__ C, int M, int N, int K) {
    __shared__ unsigned As[32][GPITCH];
    __shared__ unsigned Bs[32][GPITCH];

    const int tid = threadIdx.x;
    const int lane = tid & 31, wid = tid >> 5;
    const int wm = wid & 3, wn = wid >> 2;       // warp grid 4 (M) x 2 (N)
    const int row0 = blockIdx.y * 128, col0 = blockIdx.x * 128;

    float acc[2][8][4];
#pragma unroll
    for (int mt = 0; mt < 2; mt++)
#pragma unroll
        for (int nt = 0; nt < 8; nt++)
#pragma unroll
            for (int e = 0; e < 4; e++) acc[mt][nt][e] = 0.f;

    const float* Ag = A + (size_t)row0 * K;
    const float* Bg = B + (size_t)col0 * K;

    for (int k0 = 0; k0 < K; k0 += 32) {
        __syncthreads();
        // Load 128x32 tiles of A and B, convert to tf32, store k-major.
#pragma unroll
        for (int i = 0; i < 4; i++) {
            int lin = tid + i * 256;           // 0..1023
            int r = lin >> 3;                  // 0..127
            int c = (lin & 7) << 2;            // 0..28
            float4 va = *(const float4*)&Ag[(size_t)r * K + k0 + c];
            As[c + 0][r] = f2tf(va.x); As[c + 1][r] = f2tf(va.y);
            As[c + 2][r] = f2tf(va.z); As[c + 3][r] = f2tf(va.w);
            float4 vb = *(const float4*)&Bg[(size_t)r * K + k0 + c];
            Bs[c + 0][r] = f2tf(vb.x); Bs[c + 1][r] = f2tf(vb.y);
            Bs[c + 2][r] = f2tf(vb.z); Bs[c + 3][r] = f2tf(vb.w);
        }
        __syncthreads();

#pragma unroll
        for (int ks = 0; ks < 4; ks++) {
            const int kk = ks * 8 + (lane & 3);
            const int mrow = wm * 32 + (lane >> 2);
            const int nb = wn * 64 + (lane >> 2);
            unsigned af[2][4], bf[8][2];
#pragma unroll
            for (int mt = 0; mt < 2; mt++) {
                af[mt][0] = As[kk][mrow + mt * 16];
                af[mt][1] = As[kk][mrow + mt * 16 + 8];
                af[mt][2] = As[kk + 4][mrow + mt * 16];
                af[mt][3] = As[kk + 4][mrow + mt * 16 + 8];
            }
#pragma unroll
            for (int nt = 0; nt < 8; nt++) {
                bf[nt][0] = Bs[kk][nb + nt * 8];
                bf[nt][1] = Bs[kk + 4][nb + nt * 8];
            }
#pragma unroll
            for (int mt = 0; mt < 2; mt++)
#pragma unroll
                for (int nt = 0; nt < 8; nt++)
                    mma8(acc[mt][nt], af[mt], bf[nt]);
        }
    }

    // Writeback
#pragma unroll
    for (int mt = 0; mt < 2; mt++)
#pragma unroll
        for (int nt = 0; nt < 8; nt++) {
            int r = row0 + wm * 32 + mt * 16 + (lane >> 2);
            int cc = col0 + wn * 64 + nt * 8 + 2 * (lane & 3);
            *(float2*)&C[(size_t)r * N + cc] =
                make_float2(acc[mt][nt][0], acc[mt][nt][1]);
            *(float2*)&C[(size_t)(r + 8) * N + cc] =
                make_float2(acc[mt][nt][2], acc[mt][nt][3]);
        }
}

// ---------------------------------------------------------------------------
// RoPE in-place on q and k slices of g_qkv.
// ---------------------------------------------------------------------------
__global__ void rope_kernel(float* __restrict__ qkv, const int* __restrict__ pos) {
    int idx = blockIdx.x * blockDim.x + threadIdx.x;
    if (idx >= MTOT * NHEADS * (DK / 2)) return;
    int m = idx >> 9;
    int r = idx & 511;
    int h = r >> 5;
    int i = r & 31;

    float p = (float)pos[m];
    float inv = expf(-logf(10000.0f) * (2.0f * (float)i) / 64.0f);
    float ang = p * inv;
    float sn, cs;
    sincosf(ang, &sn, &cs);

    float* q = qkv + (size_t)m * 3072 + h * DK + 2 * i;
    float* k = q + DMODEL;
    float q1 = q[0], q2 = q[1];
    q[0] = q1 * cs - q2 * sn;
    q[1] = q1 * sn + q2 * cs;
    float k1 = k[0], k2 = k[1];
    k[0] = k1 * cs - k2 * sn;
    k[1] = k1 * sn + k2 * cs;
}

// ---------------------------------------------------------------------------
// Causal flash attention with tf32 tensor cores.
// Block: 128 threads (4 warps), BQ=64 rows (16 per warp), BKEY=64, DK=64.
// S and PV both via mma.m16n8k8; softmax fully register-resident;
// P C-fragments converted to A-fragments with quad shuffles (no smem trip).
// ---------------------------------------------------------------------------
#define QKPITCH 68
#define VPITCH 72
#define ATT_SMEM ((64 * QKPITCH * 2 + 64 * VPITCH) * 4)

__global__ __launch_bounds__(128, 4)
void flash_tf32(const float* __restrict__ qkv, float* __restrict__ out) {
    extern __shared__ unsigned smu[];
    unsigned* Qs = smu;                       // [64][68]
    unsigned* Ks = Qs + 64 * QKPITCH;         // [64][68]
    unsigned* Vs = Ks + 64 * QKPITCH;         // [64][72]

    const int qt = gridDim.x - 1 - blockIdx.x;   // heavy tiles first
    const int hh = blockIdx.y;
    const int b  = blockIdx.z;
    const int q0 = qt * 64;
    const int tid = threadIdx.x;
    const int lane = tid & 31, w = tid >> 5;
    const int qlane = lane & 3, grp = lane >> 2;

    const float* base = qkv + (size_t)b * SEQ * 3072 + hh * DK;

    // Load Q tile (pre-scaled by 1/sqrt(dk)), tf32
#pragma unroll
    for (int i = 0; i < 8; i++) {
        int lin = tid + i * 128;
        int r = lin >> 4;
        int c = (lin & 15) << 2;
        float4 v = *(const float4*)&base[(size_t)(q0 + r) * 3072 + c];
        unsigned* dst = &Qs[r * QKPITCH + c];
        dst[0] = f2tf(v.x * 0.125f); dst[1] = f2tf(v.y * 0.125f);
        dst[2] = f2tf(v.z * 0.125f); dst[3] = f2tf(v.w * 0.125f);
    }

    float o[8][4];
#pragma unroll
    for (int nt = 0; nt < 8; nt++)
#pragma unroll
        for (int e = 0; e < 4; e++) o[nt][e] = 0.f;
    float m_run[2] = {-1e30f, -1e30f};
    float l_run[2] = {0.f, 0.f};

    const int rloc = w * 16 + grp;   // local row (and rloc+8)

    for (int kt = 0; kt <= qt; kt++) {
        const int k0 = kt * 64;
        __syncthreads();
        // Load K and V tiles (tf32)
#pragma unroll
        for (int i = 0; i < 8; i++) {
            int lin = tid + i * 128;
            int r = lin >> 4;
            int c = (lin & 15) << 2;
            const float* kp = &base[(size_t)(k0 + r) * 3072 + DMODEL + c];
            float4 kv = *(const float4*)kp;
            unsigned* kd = &Ks[r * QKPITCH + c];
            kd[0] = f2tf(kv.x); kd[1] = f2tf(kv.y);
            kd[2] = f2tf(kv.z); kd[3] = f2tf(kv.w);
            float4 vv = *(const float4*)(kp + DMODEL);
            unsigned* vd = &Vs[r * VPITCH + c];
            vd[0] = f2tf(vv.x); vd[1] = f2tf(vv.y);
            vd[2] = f2tf(vv.z); vd[3] = f2tf(vv.w);
        }
        __syncthreads();

        // ---- S = Q K^T ----
        float s[8][4];
#pragma unroll
        for (int nt = 0; nt < 8; nt++)
#pragma unroll
            for (int e = 0; e < 4; e++) s[nt][e] = 0.f;

#pragma unroll
        for (int ks = 0; ks < 8; ks++) {
            int d = ks * 8 + qlane;
            unsigned qa[4];
            qa[0] = Qs[rloc * QKPITCH + d];
            qa[1] = Qs[(rloc + 8) * QKPITCH + d];
            qa[2] = Qs[rloc * QKPITCH + d + 4];
            qa[3] = Qs[(rloc + 8) * QKPITCH + d + 4];
#pragma unroll
            for (int nt = 0; nt < 8; nt++) {
                unsigned bfr[2];
                int key = nt * 8 + grp;
                bfr[0] = Ks[key * QKPITCH + d];
                bfr[1] = Ks[key * QKPITCH + d + 4];
                mma8(s[nt], qa, bfr);
            }
        }

        // ---- causal mask (diagonal tile only) ----
        if (kt == qt) {
#pragma unroll
            for (int nt = 0; nt < 8; nt++) {
                int j0 = nt * 8 + 2 * qlane;
#pragma unroll
                for (int e = 0; e < 4; e++) {
                    int i_loc = rloc + (e >> 1) * 8;
                    int j_loc = j0 + (e & 1);
                    if (j_loc > i_loc) s[nt][e] = -1e30f;
                }
            }
        }

        // ---- online softmax (register + quad-shuffle) ----
        float alpha[2];
#pragma unroll
        for (int hrow = 0; hrow < 2; hrow++) {
            float mx = -1e30f;
#pragma unroll
            for (int nt = 0; nt < 8; nt++) {
                mx = fmaxf(mx, s[nt][2 * hrow]);
                mx = fmaxf(mx, s[nt][2 * hrow + 1]);
            }
            mx = fmaxf(mx, __shfl_xor_sync(0xffffffffu, mx, 1));
            mx = fmaxf(mx, __shfl_xor_sync(0xffffffffu, mx, 2));
            float mn = fmaxf(m_run[hrow], mx);
            alpha[hrow] = __expf(m_run[hrow] - mn);
            m_run[hrow] = mn;
            float rs = 0.f;
#pragma unroll
            for (int nt = 0; nt < 8; nt++) {
                float p0 = __expf(s[nt][2 * hrow] - mn);
                float p1 = __expf(s[nt][2 * hrow + 1] - mn);
                s[nt][2 * hrow] = p0;
                s[nt][2 * hrow + 1] = p1;
                rs += p0 + p1;
            }
            rs += __shfl_xor_sync(0xffffffffu, rs, 1);
            rs += __shfl_xor_sync(0xffffffffu, rs, 2);
            l_run[hrow] = l_run[hrow] * alpha[hrow] + rs;
        }
#pragma unroll
        for (int nt = 0; nt < 8; nt++) {
            o[nt][0] *= alpha[0]; o[nt][1] *= alpha[0];
            o[nt][2] *= alpha[1]; o[nt][3] *= alpha[1];
        }

        // ---- O += P V : convert P C-frags -> A-frags via quad shuffles ----
        const int src0 = (lane & ~3) | (qlane >> 1);
        const int src1 = src0 + 2;
#pragma unroll
        for (int ks = 0; ks < 8; ks++) {
            float v00 = __shfl_sync(0xffffffffu, s[ks][0], src0);
            float v01 = __shfl_sync(0xffffffffu, s[ks][1], src0);
            float v20 = __shfl_sync(0xffffffffu, s[ks][2], src0);
            float v21 = __shfl_sync(0xffffffffu, s[ks][3], src0);
            float v02 = __shfl_sync(0xffffffffu, s[ks][0], src1);
            float v03 = __shfl_sync(0xffffffffu, s[ks][1], src1);
            float v22 = __shfl_sync(0xffffffffu, s[ks][2], src1);
            float v23 = __shfl_sync(0xffffffffu, s[ks][3], src1);
            unsigned pa[4];
            pa[0] = f2tf((qlane & 1) ? v01 : v00);  // (row r,   key ks*8+q)
            pa[1] = f2tf((qlane & 1) ? v21 : v20);  // (row r+8, key ks*8+q)
            pa[2] = f2tf((qlane & 1) ? v03 : v02);  // (row r,   key ks*8+q+4)
            pa[3] = f2tf((qlane & 1) ? v23 : v22);  // (row r+8, key ks*8+q+4)
            int kr = ks * 8 + qlane;
#pragma unroll
            for (int nt = 0; nt < 8; nt++) {
                unsigned vb[2];
                vb[0] = Vs[kr * VPITCH + nt * 8 + grp];
                vb[1] = Vs[(kr + 4) * VPITCH + nt * 8 + grp];
                mma8(o[nt], pa, vb);
            }
        }
    }

    // Epilogue
    float inv0 = 1.f / l_run[0];
    float inv1 = 1.f / l_run[1];
    float* op = out + ((size_t)(b * SEQ + q0)) * DMODEL + hh * DK;
#pragma unroll
    for (int nt = 0; nt < 8; nt++) {
        int cc = nt * 8 + 2 * qlane;
        *(float2*)&op[(size_t)rloc * DMODEL + cc] =
            make_float2(o[nt][0] * inv0, o[nt][1] * inv0);
        *(float2*)&op[(size_t)(rloc + 8) * DMODEL + cc] =
            make_float2(o[nt][2] * inv1, o[nt][3] * inv1);
    }
}

// ---------------------------------------------------------------------------
// Launch
// ---------------------------------------------------------------------------
extern "C" void kernel_launch(void* const* d_in, const int* in_sizes, int n_in,
                              void* d_out, int out_size) {
    const float* x     = (const float*)d_in[0];
    const int*   pos   = (const int*)d_in[1];
    const float* w_qkv = (const float*)d_in[2];
    const float* w_o   = (const float*)d_in[3];
    float* out = (float*)d_out;

    float* qkv = nullptr;
    float* attn = nullptr;
    cudaGetSymbolAddress((void**)&qkv, g_qkv);
    cudaGetSymbolAddress((void**)&attn, g_attn);

    // 1) QKV projection
    gemm_tf32<<<dim3(3 * DMODEL / 128, MTOT / 128), 256>>>(x, w_qkv, qkv,
                                                           MTOT, 3 * DMODEL, DMODEL);
    // 2) RoPE
    {
        int total = MTOT * NHEADS * (DK / 2);
        rope_kernel<<<(total + 255) / 256, 256>>>(qkv, pos);
    }
    // 3) Flash attention (tf32 tensor cores)
    {
        cudaFuncSetAttribute(flash_tf32,
                             cudaFuncAttributeMaxDynamicSharedMemorySize, ATT_SMEM);
        flash_tf32<<<dim3(SEQ / 64, NHEADS, BATCH), 128, ATT_SMEM>>>(qkv, attn);
    }
    // 4) Output projection
    gemm_tf32<<<dim3(DMODEL / 128, MTOT / 128), 256>>>(attn, w_o, out,
                                                       MTOT, DMODEL, DMODEL);
}

// round 3
// speedup vs baseline: 5.0206x; 1.3726x over previous
#include <cuda_runtime.h>
#include <math.h>

#define BATCH 4
#define SEQ 2048
#define DMODEL 1024
#define NHEADS 16
#define DK 64
#define MTOT (BATCH * SEQ)   // 8192

// Scratch (module-load allocated)
__device__ float g_qkv[(size_t)MTOT * 3 * DMODEL];   // [8192, 3072]
__device__ float g_attn[(size_t)MTOT * DMODEL];      // [8192, 1024]

// ---------------------------------------------------------------------------
// tf32 helpers
// ---------------------------------------------------------------------------
__device__ __forceinline__ unsigned f2tf(float f) {
    unsigned r;
    asm("cvt.rna.tf32.f32 %0, %1;" : "=r"(r) : "f"(f));
    return r;
}

__device__ __forceinline__ void mma8(float* c, const unsigned* a, const unsigned* b) {
    asm volatile(
        "mma.sync.aligned.m16n8k8.row.col.f32.tf32.tf32.f32 "
        "{%0,%1,%2,%3},{%4,%5,%6,%7},{%8,%9},{%0,%1,%2,%3};"
        : "+f"(c[0]), "+f"(c[1]), "+f"(c[2]), "+f"(c[3])
        : "r"(a[0]), "r"(a[1]), "r"(a[2]), "r"(a[3]), "r"(b[0]), "r"(b[1]));
}

// ---------------------------------------------------------------------------
// GEMM C[M,N] = A[M,K] * B[N,K]^T via tf32 mma, fragment-order smem +
// register-prefetch pipeline. Block 128x128, BK=32, 256 threads (8 warps 4x2),
// warp tile 32x64.
//
// Fragment layout:
//   A tile 128x32 -> 8 mt x 4 kt frags of 16x8; frag fa = mt*4+kt,
//     word addr = fa*FSA + lane*4 + reg  (reg = (row>>3) | ((k>>2)<<1),
//     lane = (row&7)*4 + (k&3))         -> compute load = 1 x LDS.128
//   B tile 128x32 -> 16 nt x 4 kt frags of 8x8; frag fb = nt*4+kt,
//     word addr = fb*FSB + lane*2 + reg (reg = (k>>2)&1, lane = (n&7)*4+(k&3))
//                                        -> compute load = 1 x LDS.64
// ---------------------------------------------------------------------------
#define FSA 132
#define FSB 66

__global__ __launch_bounds__(256, 2)
void gemm_tf32(const float* __restrict__ A, const float* __restrict__ B,
               float* __restrict__ C, int M, int N, int K) {
    __shared__ unsigned As[32 * FSA];
    __shared__ unsigned Bs[64 * FSB];

    const int tid = threadIdx.x;
    const int lane = tid & 31, wid = tid >> 5;
    const int wm = wid & 3, wn = wid >> 2;
    const int row0 = blockIdx.y * 128, col0 = blockIdx.x * 128;

    float acc[2][8][4];
#pragma unroll
    for (int mt = 0; mt < 2; mt++)
#pragma unroll
        for (int nt = 0; nt < 8; nt++)
#pragma unroll
            for (int e = 0; e < 4; e++) acc[mt][nt][e] = 0.f;

    const float* Ag = A + (size_t)row0 * K;
    const float* Bg = B + (size_t)col0 * K;

    const int rbase = tid >> 3;          // 0..31, full row = rbase + i*32
    const int c = (tid & 7) << 2;        // 0,4,...,28

    float4 ra[4], rb[4];
#pragma unroll
    for (int i = 0; i < 4; i++) {
        int rr = rbase + i * 32;
        ra[i] = *(const float4*)&Ag[(size_t)rr * K + c];
        rb[i] = *(const float4*)&Bg[(size_t)rr * K + c];
    }

    for (int k0 = 0; k0 < K; k0 += 32) {
        __syncthreads();
        // Store staged registers as fragments
#pragma unroll
        for (int i = 0; i < 4; i++) {
            int rr = rbase + i * 32;
            int fa = (rr >> 4) * 4 + (c >> 3);
            int areg = ((rr >> 3) & 1) | (((c >> 2) & 1) << 1);
            unsigned* pa = &As[fa * FSA + (rr & 7) * 16 + areg];
            pa[0]  = f2tf(ra[i].x); pa[4]  = f2tf(ra[i].y);
            pa[8]  = f2tf(ra[i].z); pa[12] = f2tf(ra[i].w);
            int fb = (rr >> 3) * 4 + (c >> 3);
            int breg = (c >> 2) & 1;
            unsigned* pb = &Bs[fb * FSB + (rr & 7) * 8 + breg];
            pb[0] = f2tf(rb[i].x); pb[2] = f2tf(rb[i].y);
            pb[4] = f2tf(rb[i].z); pb[6] = f2tf(rb[i].w);
        }
        __syncthreads();

        // Prefetch next k-tile into registers (overlaps with compute below)
        if (k0 + 32 < K) {
#pragma unroll
            for (int i = 0; i < 4; i++) {
                int rr = rbase + i * 32;
                ra[i] = *(const float4*)&Ag[(size_t)rr * K + k0 + 32 + c];
                rb[i] = *(const float4*)&Bg[(size_t)rr * K + k0 + 32 + c];
            }
        }

        // Compute
#pragma unroll
        for (int ks = 0; ks < 4; ks++) {
            unsigned af[2][4], bf[8][2];
#pragma unroll
            for (int mt = 0; mt < 2; mt++) {
                int fa = (wm * 2 + mt) * 4 + ks;
                *(uint4*)af[mt] = *(const uint4*)&As[fa * FSA + lane * 4];
            }
#pragma unroll
            for (int nt = 0; nt < 8; nt++) {
                int fb = (wn * 8 + nt) * 4 + ks;
                *(uint2*)bf[nt] = *(const uint2*)&Bs[fb * FSB + lane * 2];
            }
#pragma unroll
            for (int mt = 0; mt < 2; mt++)
#pragma unroll
                for (int nt = 0; nt < 8; nt++)
                    mma8(acc[mt][nt], af[mt], bf[nt]);
        }
    }

    // Writeback
#pragma unroll
    for (int mt = 0; mt < 2; mt++)
#pragma unroll
        for (int nt = 0; nt < 8; nt++) {
            int r = row0 + wm * 32 + mt * 16 + (lane >> 2);
            int cc = col0 + wn * 64 + nt * 8 + 2 * (lane & 3);
            *(float2*)&C[(size_t)r * N + cc] =
                make_float2(acc[mt][nt][0], acc[mt][nt][1]);
            *(float2*)&C[(size_t)(r + 8) * N + cc] =
                make_float2(acc[mt][nt][2], acc[mt][nt][3]);
        }
}

// ---------------------------------------------------------------------------
// RoPE in-place on q and k slices of g_qkv.
// ---------------------------------------------------------------------------
__global__ void rope_kernel(float* __restrict__ qkv, const int* __restrict__ pos) {
    int idx = blockIdx.x * blockDim.x + threadIdx.x;
    if (idx >= MTOT * NHEADS * (DK / 2)) return;
    int m = idx >> 9;
    int r = idx & 511;
    int h = r >> 5;
    int i = r & 31;

    float p = (float)pos[m];
    float inv = expf(-logf(10000.0f) * (2.0f * (float)i) / 64.0f);
    float ang = p * inv;
    float sn, cs;
    sincosf(ang, &sn, &cs);

    float* q = qkv + (size_t)m * 3072 + h * DK + 2 * i;
    float* k = q + DMODEL;
    float q1 = q[0], q2 = q[1];
    q[0] = q1 * cs - q2 * sn;
    q[1] = q1 * sn + q2 * cs;
    float k1 = k[0], k2 = k[1];
    k[0] = k1 * cs - k2 * sn;
    k[1] = k1 * sn + k2 * cs;
}

// ---------------------------------------------------------------------------
// Causal flash attention, tf32 tensor cores.
// Block: 256 threads (8 warps), BQ=128 q-rows (16 per warp), BKEY=64.
// Register-prefetch pipeline on K/V tiles; per-warp skip of fully-masked tiles.
// ---------------------------------------------------------------------------
#define QKPITCH 68
#define VPITCH 72
#define ATT_SMEM ((128 * QKPITCH + 64 * QKPITCH + 64 * VPITCH) * 4)

__global__ __launch_bounds__(256, 2)
void flash_tf32(const float* __restrict__ qkv, float* __restrict__ out) {
    extern __shared__ unsigned smu[];
    unsigned* Qs = smu;                        // [128][68]
    unsigned* Ks = Qs + 128 * QKPITCH;         // [64][68]
    unsigned* Vs = Ks + 64 * QKPITCH;          // [64][72]

    const int qb = gridDim.x - 1 - blockIdx.x;   // heavy tiles first
    const int hh = blockIdx.y;
    const int b  = blockIdx.z;
    const int q0 = qb * 128;
    const int tid = threadIdx.x;
    const int lane = tid & 31, w = tid >> 5;
    const int qlane = lane & 3, grp = lane >> 2;

    const float* base = qkv + (size_t)b * SEQ * 3072 + hh * DK;

    // Load Q tile (pre-scaled by 1/sqrt(dk)), tf32
#pragma unroll
    for (int i = 0; i < 8; i++) {
        int lin = tid + i * 256;
        int r = lin >> 4;
        int cc = (lin & 15) << 2;
        float4 v = *(const float4*)&base[(size_t)(q0 + r) * 3072 + cc];
        unsigned* dst = &Qs[r * QKPITCH + cc];
        dst[0] = f2tf(v.x * 0.125f); dst[1] = f2tf(v.y * 0.125f);
        dst[2] = f2tf(v.z * 0.125f); dst[3] = f2tf(v.w * 0.125f);
    }

    float o[8][4];
#pragma unroll
    for (int nt = 0; nt < 8; nt++)
#pragma unroll
        for (int e = 0; e < 4; e++) o[nt][e] = 0.f;
    float m_run[2] = {-1e30f, -1e30f};
    float l_run[2] = {0.f, 0.f};

    const int rloc = w * 16 + grp;   // this thread's rows: rloc, rloc+8
    const int ktiles = (q0 >> 6) + 2;

    float4 rk[4], rv[4];
    // Prefetch K/V tile 0
#pragma unroll
    for (int i = 0; i < 4; i++) {
        int lin = tid + i * 256;
        int r = lin >> 4;
        int cc = (lin & 15) << 2;
        const float* kp = &base[(size_t)r * 3072 + DMODEL + cc];
        rk[i] = *(const float4*)kp;
        rv[i] = *(const float4*)(kp + DMODEL);
    }

    for (int kt = 0; kt < ktiles; kt++) {
        const int k0 = kt * 64;
        __syncthreads();
        // Store staged K/V (tf32)
#pragma unroll
        for (int i = 0; i < 4; i++) {
            int lin = tid + i * 256;
            int r = lin >> 4;
            int cc = (lin & 15) << 2;
            unsigned* kd = &Ks[r * QKPITCH + cc];
            kd[0] = f2tf(rk[i].x); kd[1] = f2tf(rk[i].y);
            kd[2] = f2tf(rk[i].z); kd[3] = f2tf(rk[i].w);
            unsigned* vd = &Vs[r * VPITCH + cc];
            vd[0] = f2tf(rv[i].x); vd[1] = f2tf(rv[i].y);
            vd[2] = f2tf(rv[i].z); vd[3] = f2tf(rv[i].w);
        }
        __syncthreads();

        // Prefetch next K/V tile (overlaps compute)
        if (kt + 1 < ktiles) {
            const int kn = (kt + 1) * 64;
#pragma unroll
            for (int i = 0; i < 4; i++) {
                int lin = tid + i * 256;
                int r = lin >> 4;
                int cc = (lin & 15) << 2;
                const float* kp = &base[(size_t)(kn + r) * 3072 + DMODEL + cc];
                rk[i] = *(const float4*)kp;
                rv[i] = *(const float4*)(kp + DMODEL);
            }
        }

        // Per-warp causal skip: warp rows q0+w*16 .. q0+w*16+15
        if (k0 <= q0 + w * 16 + 15) {
            // ---- S = Q K^T ----
            float s[8][4];
#pragma unroll
            for (int nt = 0; nt < 8; nt++)
#pragma unroll
                for (int e = 0; e < 4; e++) s[nt][e] = 0.f;

#pragma unroll
            for (int ks = 0; ks < 8; ks++) {
                int d = ks * 8 + qlane;
                unsigned qa[4];
                qa[0] = Qs[rloc * QKPITCH + d];
                qa[1] = Qs[(rloc + 8) * QKPITCH + d];
                qa[2] = Qs[rloc * QKPITCH + d + 4];
                qa[3] = Qs[(rloc + 8) * QKPITCH + d + 4];
#pragma unroll
                for (int nt = 0; nt < 8; nt++) {
                    unsigned bfr[2];
                    int key = nt * 8 + grp;
                    bfr[0] = Ks[key * QKPITCH + d];
                    bfr[1] = Ks[key * QKPITCH + d + 4];
                    mma8(s[nt], qa, bfr);
                }
            }

            // ---- causal mask (tiles overlapping the diagonal) ----
            if (k0 + 63 > q0 + w * 16) {
                int i0 = q0 + rloc;
#pragma unroll
                for (int nt = 0; nt < 8; nt++) {
                    int j0 = k0 + nt * 8 + 2 * qlane;
                    if (j0 > i0)     s[nt][0] = -1e30f;
                    if (j0 + 1 > i0) s[nt][1] = -1e30f;
                    if (j0 > i0 + 8)     s[nt][2] = -1e30f;
                    if (j0 + 1 > i0 + 8) s[nt][3] = -1e30f;
                }
            }

            // ---- online softmax ----
            float alpha[2];
#pragma unroll
            for (int hrow = 0; hrow < 2; hrow++) {
                float mx = -1e30f;
#pragma unroll
                for (int nt = 0; nt < 8; nt++) {
                    mx = fmaxf(mx, s[nt][2 * hrow]);
                    mx = fmaxf(mx, s[nt][2 * hrow + 1]);
                }
                mx = fmaxf(mx, __shfl_xor_sync(0xffffffffu, mx, 1));
                mx = fmaxf(mx, __shfl_xor_sync(0xffffffffu, mx, 2));
                float mn = fmaxf(m_run[hrow], mx);
                alpha[hrow] = __expf(m_run[hrow] - mn);
                m_run[hrow] = mn;
                float rs = 0.f;
#pragma unroll
                for (int nt = 0; nt < 8; nt++) {
                    float p0 = __expf(s[nt][2 * hrow] - mn);
                    float p1 = __expf(s[nt][2 * hrow + 1] - mn);
                    s[nt][2 * hrow] = p0;
                    s[nt][2 * hrow + 1] = p1;
                    rs += p0 + p1;
                }
                rs += __shfl_xor_sync(0xffffffffu, rs, 1);
                rs += __shfl_xor_sync(0xffffffffu, rs, 2);
                l_run[hrow] = l_run[hrow] * alpha[hrow] + rs;
            }
#pragma unroll
            for (int nt = 0; nt < 8; nt++) {
                o[nt][0] *= alpha[0]; o[nt][1] *= alpha[0];
                o[nt][2] *= alpha[1]; o[nt][3] *= alpha[1];
            }

            // ---- O += P V (P C-frags -> A-frags via quad shuffles) ----
            const int src0 = (lane & ~3) | (qlane >> 1);
            const int src1 = src0 + 2;
#pragma unroll
            for (int ks = 0; ks < 8; ks++) {
                float v00 = __shfl_sync(0xffffffffu, s[ks][0], src0);
                float v01 = __shfl_sync(0xffffffffu, s[ks][1], src0);
                float v20 = __shfl_sync(0xffffffffu, s[ks][2], src0);
                float v21 = __shfl_sync(0xffffffffu, s[ks][3], src0);
                float v02 = __shfl_sync(0xffffffffu, s[ks][0], src1);
                float v03 = __shfl_sync(0xffffffffu, s[ks][1], src1);
                float v22 = __shfl_sync(0xffffffffu, s[ks][2], src1);
                float v23 = __shfl_sync(0xffffffffu, s[ks][3], src1);
                unsigned pa[4];
                pa[0] = f2tf((qlane & 1) ? v01 : v00);
                pa[1] = f2tf((qlane & 1) ? v21 : v20);
                pa[2] = f2tf((qlane & 1) ? v03 : v02);
                pa[3] = f2tf((qlane & 1) ? v23 : v22);
                int kr = ks * 8 + qlane;
#pragma unroll
                for (int nt = 0; nt < 8; nt++) {
                    unsigned vb[2];
                    vb[0] = Vs[kr * VPITCH + nt * 8 + grp];
                    vb[1] = Vs[(kr + 4) * VPITCH + nt * 8 + grp];
                    mma8(o[nt], pa, vb);
                }
            }
        }
    }

    // Epilogue
    float inv0 = 1.f / l_run[0];
    float inv1 = 1.f / l_run[1];
    float* op = out + ((size_t)(b * SEQ + q0)) * DMODEL + hh * DK;
#pragma unroll
    for (int nt = 0; nt < 8; nt++) {
        int cc = nt * 8 + 2 * qlane;
        *(float2*)&op[(size_t)rloc * DMODEL + cc] =
            make_float2(o[nt][0] * inv0, o[nt][1] * inv0);
        *(float2*)&op[(size_t)(rloc + 8) * DMODEL + cc] =
            make_float2(o[nt][2] * inv1, o[nt][3] * inv1);
    }
}

// ---------------------------------------------------------------------------
// Launch
// ---------------------------------------------------------------------------
extern "C" void kernel_launch(void* const* d_in, const int* in_sizes, int n_in,
                              void* d_out, int out_size) {
    const float* x     = (const float*)d_in[0];
    const int*   pos   = (const int*)d_in[1];
    const float* w_qkv = (const float*)d_in[2];
    const float* w_o   = (const float*)d_in[3];
    float* out = (float*)d_out;

    float* qkv = nullptr;
    float* attn = nullptr;
    cudaGetSymbolAddress((void**)&qkv, g_qkv);
    cudaGetSymbolAddress((void**)&attn, g_attn);

    // 1) QKV projection
    gemm_tf32<<<dim3(3 * DMODEL / 128, MTOT / 128), 256>>>(x, w_qkv, qkv,
                                                           MTOT, 3 * DMODEL, DMODEL);
    // 2) RoPE
    {
        int total = MTOT * NHEADS * (DK / 2);
        rope_kernel<<<(total + 255) / 256, 256>>>(qkv, pos);
    }
    // 3) Flash attention
    {
        cudaFuncSetAttribute(flash_tf32,
                             cudaFuncAttributeMaxDynamicSharedMemorySize, ATT_SMEM);
        flash_tf32<<<dim3(SEQ / 128, NHEADS, BATCH), 256, ATT_SMEM>>>(qkv, attn);
    }
    // 4) Output projection
    gemm_tf32<<<dim3(DMODEL / 128, MTOT / 128), 256>>>(attn, w_o, out,
                                                       MTOT, DMODEL, DMODEL);
}

// round 4
// speedup vs baseline: 5.7753x; 1.1503x over previous
#include <cuda_runtime.h>
#include <math.h>

#define BATCH 4
#define SEQ 2048
#define DMODEL 1024
#define NHEADS 16
#define DK 64
#define MTOT (BATCH * SEQ)   // 8192

// Scratch (module-load allocated)
__device__ float    g_qkv[(size_t)MTOT * 3 * DMODEL];        // [8192,3072] row-major
__device__ unsigned g_xpack[(size_t)MTOT * DMODEL];          // x, tf32 fragment-packed
__device__ unsigned g_wqkv_pack[(size_t)3 * DMODEL * DMODEL];
__device__ unsigned g_wo_pack[(size_t)DMODEL * DMODEL];
__device__ unsigned g_attn_pack[(size_t)MTOT * DMODEL];      // attn out, fragment-packed

// ---------------------------------------------------------------------------
// tf32 / mma / cp.async helpers
// ---------------------------------------------------------------------------
__device__ __forceinline__ unsigned f2tf(float f) {
    unsigned r;
    asm("cvt.rna.tf32.f32 %0, %1;" : "=r"(r) : "f"(f));
    return r;
}

__device__ __forceinline__ void mma8(float* c, const unsigned* a, const unsigned* b) {
    asm volatile(
        "mma.sync.aligned.m16n8k8.row.col.f32.tf32.tf32.f32 "
        "{%0,%1,%2,%3},{%4,%5,%6,%7},{%8,%9},{%0,%1,%2,%3};"
        : "+f"(c[0]), "+f"(c[1]), "+f"(c[2]), "+f"(c[3])
        : "r"(a[0]), "r"(a[1]), "r"(a[2]), "r"(a[3]), "r"(b[0]), "r"(b[1]));
}

__device__ __forceinline__ void cp_async16(unsigned* smem_ptr, const unsigned* gptr) {
    unsigned sa = (unsigned)__cvta_generic_to_shared(smem_ptr);
    asm volatile("cp.async.cg.shared.global [%0], [%1], 16;" :: "r"(sa), "l"(gptr));
}
__device__ __forceinline__ void cp_commit() {
    asm volatile("cp.async.commit_group;");
}
__device__ __forceinline__ void cp_wait1() {
    asm volatile("cp.async.wait_group 1;");
}

// Fragment-packed layouts (per 128x32 tile = 4096 words):
//  A (16x8 frags): word = ((r>>4)*4 + (kl>>3))*128 + ((r&7)*4 + (kl&3))*4
//                         + (((r>>3)&1) | (((kl>>2)&1)<<1))
//  B (8x8 frags):  word = (((n>>3)*4 + (kl>>3)))*64 + ((n&7)*4 + (kl&3))*2
//                         + ((kl>>2)&1)
__device__ __forceinline__ int a_word(int r, int kl) {
    return ((r >> 4) * 4 + (kl >> 3)) * 128 + ((r & 7) * 4 + (kl & 3)) * 4 +
           (((r >> 3) & 1) | (((kl >> 2) & 1) << 1));
}
__device__ __forceinline__ int b_word(int n, int kl) {
    return ((n >> 3) * 4 + (kl >> 3)) * 64 + ((n & 7) * 4 + (kl & 3)) * 2 +
           ((kl >> 2) & 1);
}

// ---------------------------------------------------------------------------
// Pack kernels: row-major fp32 -> tf32 fragment-packed global
// ---------------------------------------------------------------------------
__global__ void pack_a_kernel(const float* __restrict__ src, unsigned* __restrict__ dst,
                              int ROWS, int K) {
    int idx = blockIdx.x * blockDim.x + threadIdx.x;
    int K4 = K >> 2;
    if (idx >= ROWS * K4) return;
    int rg = idx / K4;
    int c0 = (idx - rg * K4) << 2;
    float4 v = *(const float4*)&src[(size_t)rg * K + c0];
    int rp = rg >> 7, r = rg & 127, kp = c0 >> 5;
    size_t tile = ((size_t)rp * (K >> 5) + kp) * 4096;
    float vv[4] = {v.x, v.y, v.z, v.w};
#pragma unroll
    for (int j = 0; j < 4; j++) {
        int kl = (c0 & 31) + j;
        dst[tile + a_word(r, kl)] = f2tf(vv[j]);
    }
}

__global__ void pack_b_kernel(const float* __restrict__ src, unsigned* __restrict__ dst,
                              int ROWS, int K) {
    int idx = blockIdx.x * blockDim.x + threadIdx.x;
    int K4 = K >> 2;
    if (idx >= ROWS * K4) return;
    int ng = idx / K4;
    int c0 = (idx - ng * K4) << 2;
    float4 v = *(const float4*)&src[(size_t)ng * K + c0];
    int np = ng >> 7, n = ng & 127, kp = c0 >> 5;
    size_t tile = ((size_t)np * (K >> 5) + kp) * 4096;
    float vv[4] = {v.x, v.y, v.z, v.w};
#pragma unroll
    for (int j = 0; j < 4; j++) {
        int kl = (c0 & 31) + j;
        dst[tile + b_word(n, kl)] = f2tf(vv[j]);
    }
}

// ---------------------------------------------------------------------------
// GEMM on packed operands: C[M,N] = A * B^T, 128x128 tiles, BK=32,
// 256 threads (8 warps 4x2), 3-stage cp.async pipeline.
// Stage = A tile (4096 w) + B tile (4096 w) = 32 KB.
// ---------------------------------------------------------------------------
#define GEMM_SMEM (3 * 8192 * 4)

__device__ __forceinline__ void issue_stage(unsigned* smbase,
                                            const unsigned* __restrict__ Ap,
                                            const unsigned* __restrict__ Bp,
                                            int kt, int tid) {
    const unsigned* ga = Ap + (size_t)kt * 4096;
    const unsigned* gb = Bp + (size_t)kt * 4096;
#pragma unroll
    for (int i = 0; i < 4; i++) {
        int c = (tid + i * 256) * 4;
        cp_async16(smbase + c, ga + c);
        cp_async16(smbase + 4096 + c, gb + c);
    }
}

__global__ __launch_bounds__(256, 2)
void gemm_packed(const unsigned* __restrict__ Apack, const unsigned* __restrict__ Bpack,
                 float* __restrict__ C, int M, int N, int K) {
    extern __shared__ unsigned sm[];
    const int tid = threadIdx.x;
    const int lane = tid & 31, wid = tid >> 5;
    const int wm = wid & 3, wn = wid >> 2;
    const int KT = K >> 5;

    const unsigned* Ap = Apack + (size_t)blockIdx.y * KT * 4096;
    const unsigned* Bp = Bpack + (size_t)blockIdx.x * KT * 4096;

    float acc[2][8][4];
#pragma unroll
    for (int mt = 0; mt < 2; mt++)
#pragma unroll
        for (int nt = 0; nt < 8; nt++)
#pragma unroll
            for (int e = 0; e < 4; e++) acc[mt][nt][e] = 0.f;

    // Prologue: stages 0,1 in flight
    issue_stage(sm, Ap, Bp, 0, tid); cp_commit();
    issue_stage(sm + 8192, Ap, Bp, 1, tid); cp_commit();

    for (int kt = 0; kt < KT; kt++) {
        cp_wait1();
        __syncthreads();
        if (kt + 2 < KT)
            issue_stage(sm + ((kt + 2) % 3) * 8192, Ap, Bp, kt + 2, tid);
        cp_commit();

        const unsigned* As = sm + (kt % 3) * 8192;
        const unsigned* Bs = As + 4096;
#pragma unroll
        for (int ks = 0; ks < 4; ks++) {
            unsigned af[2][4], bf[8][2];
#pragma unroll
            for (int mt = 0; mt < 2; mt++)
                *(uint4*)af[mt] =
                    *(const uint4*)&As[((wm * 2 + mt) * 4 + ks) * 128 + lane * 4];
#pragma unroll
            for (int nt = 0; nt < 8; nt++)
                *(uint2*)bf[nt] =
                    *(const uint2*)&Bs[((wn * 8 + nt) * 4 + ks) * 64 + lane * 2];
#pragma unroll
            for (int mt = 0; mt < 2; mt++)
#pragma unroll
                for (int nt = 0; nt < 8; nt++)
                    mma8(acc[mt][nt], af[mt], bf[nt]);
        }
        __syncthreads();
    }

    const int row0 = blockIdx.y * 128, col0 = blockIdx.x * 128;
#pragma unroll
    for (int mt = 0; mt < 2; mt++)
#pragma unroll
        for (int nt = 0; nt < 8; nt++) {
            int r = row0 + wm * 32 + mt * 16 + (lane >> 2);
            int cc = col0 + wn * 64 + nt * 8 + 2 * (lane & 3);
            *(float2*)&C[(size_t)r * N + cc] =
                make_float2(acc[mt][nt][0], acc[mt][nt][1]);
            *(float2*)&C[(size_t)(r + 8) * N + cc] =
                make_float2(acc[mt][nt][2], acc[mt][nt][3]);
        }
}

// ---------------------------------------------------------------------------
// RoPE in-place on q and k slices of g_qkv.
// ---------------------------------------------------------------------------
__global__ void rope_kernel(float* __restrict__ qkv, const int* __restrict__ pos) {
    int idx = blockIdx.x * blockDim.x + threadIdx.x;
    if (idx >= MTOT * NHEADS * (DK / 2)) return;
    int m = idx >> 9;
    int r = idx & 511;
    int h = r >> 5;
    int i = r & 31;

    float p = (float)pos[m];
    float inv = expf(-logf(10000.0f) * (2.0f * (float)i) / 64.0f);
    float ang = p * inv;
    float sn, cs;
    sincosf(ang, &sn, &cs);

    float* q = qkv + (size_t)m * 3072 + h * DK + 2 * i;
    float* k = q + DMODEL;
    float q1 = q[0], q2 = q[1];
    q[0] = q1 * cs - q2 * sn;
    q[1] = q1 * sn + q2 * cs;
    float k1 = k[0], k2 = k[1];
    k[0] = k1 * cs - k2 * sn;
    k[1] = k1 * sn + k2 * cs;
}

// ---------------------------------------------------------------------------
// Causal flash attention, tf32 tensor cores (same core as R3).
// Epilogue writes DIRECTLY in fragment-packed layout for the out-proj GEMM.
// ---------------------------------------------------------------------------
#define QKPITCH 68
#define VPITCH 72
#define ATT_SMEM ((128 * QKPITCH + 64 * QKPITCH + 64 * VPITCH) * 4)

__global__ __launch_bounds__(256, 2)
void flash_tf32(const float* __restrict__ qkv, unsigned* __restrict__ outp) {
    extern __shared__ unsigned smu[];
    unsigned* Qs = smu;                        // [128][68]
    unsigned* Ks = Qs + 128 * QKPITCH;         // [64][68]
    unsigned* Vs = Ks + 64 * QKPITCH;          // [64][72]

    const int qb = gridDim.x - 1 - blockIdx.x;   // heavy tiles first
    const int hh = blockIdx.y;
    const int b  = blockIdx.z;
    const int q0 = qb * 128;
    const int tid = threadIdx.x;
    const int lane = tid & 31, w = tid >> 5;
    const int qlane = lane & 3, grp = lane >> 2;

    const float* base = qkv + (size_t)b * SEQ * 3072 + hh * DK;

#pragma unroll
    for (int i = 0; i < 8; i++) {
        int lin = tid + i * 256;
        int r = lin >> 4;
        int cc = (lin & 15) << 2;
        float4 v = *(const float4*)&base[(size_t)(q0 + r) * 3072 + cc];
        unsigned* dst = &Qs[r * QKPITCH + cc];
        dst[0] = f2tf(v.x * 0.125f); dst[1] = f2tf(v.y * 0.125f);
        dst[2] = f2tf(v.z * 0.125f); dst[3] = f2tf(v.w * 0.125f);
    }

    float o[8][4];
#pragma unroll
    for (int nt = 0; nt < 8; nt++)
#pragma unroll
        for (int e = 0; e < 4; e++) o[nt][e] = 0.f;
    float m_run[2] = {-1e30f, -1e30f};
    float l_run[2] = {0.f, 0.f};

    const int rloc = w * 16 + grp;
    const int ktiles = (q0 >> 6) + 2;

    float4 rk[4], rv[4];
#pragma unroll
    for (int i = 0; i < 4; i++) {
        int lin = tid + i * 256;
        int r = lin >> 4;
        int cc = (lin & 15) << 2;
        const float* kp = &base[(size_t)r * 3072 + DMODEL + cc];
        rk[i] = *(const float4*)kp;
        rv[i] = *(const float4*)(kp + DMODEL);
    }

    for (int kt = 0; kt < ktiles; kt++) {
        const int k0 = kt * 64;
        __syncthreads();
#pragma unroll
        for (int i = 0; i < 4; i++) {
            int lin = tid + i * 256;
            int r = lin >> 4;
            int cc = (lin & 15) << 2;
            unsigned* kd = &Ks[r * QKPITCH + cc];
            kd[0] = f2tf(rk[i].x); kd[1] = f2tf(rk[i].y);
            kd[2] = f2tf(rk[i].z); kd[3] = f2tf(rk[i].w);
            unsigned* vd = &Vs[r * VPITCH + cc];
            vd[0] = f2tf(rv[i].x); vd[1] = f2tf(rv[i].y);
            vd[2] = f2tf(rv[i].z); vd[3] = f2tf(rv[i].w);
        }
        __syncthreads();

        if (kt + 1 < ktiles) {
            const int kn = (kt + 1) * 64;
#pragma unroll
            for (int i = 0; i < 4; i++) {
                int lin = tid + i * 256;
                int r = lin >> 4;
                int cc = (lin & 15) << 2;
                const float* kp = &base[(size_t)(kn + r) * 3072 + DMODEL + cc];
                rk[i] = *(const float4*)kp;
                rv[i] = *(const float4*)(kp + DMODEL);
            }
        }

        if (k0 <= q0 + w * 16 + 15) {
            float s[8][4];
#pragma unroll
            for (int nt = 0; nt < 8; nt++)
#pragma unroll
                for (int e = 0; e < 4; e++) s[nt][e] = 0.f;

#pragma unroll
            for (int ks = 0; ks < 8; ks++) {
                int d = ks * 8 + qlane;
                unsigned qa[4];
                qa[0] = Qs[rloc * QKPITCH + d];
                qa[1] = Qs[(rloc + 8) * QKPITCH + d];
                qa[2] = Qs[rloc * QKPITCH + d + 4];
                qa[3] = Qs[(rloc + 8) * QKPITCH + d + 4];
#pragma unroll
                for (int nt = 0; nt < 8; nt++) {
                    unsigned bfr[2];
                    int key = nt * 8 + grp;
                    bfr[0] = Ks[key * QKPITCH + d];
                    bfr[1] = Ks[key * QKPITCH + d + 4];
                    mma8(s[nt], qa, bfr);
                }
            }

            if (k0 + 63 > q0 + w * 16) {
                int i0 = q0 + rloc;
#pragma unroll
                for (int nt = 0; nt < 8; nt++) {
                    int j0 = k0 + nt * 8 + 2 * qlane;
                    if (j0 > i0)     s[nt][0] = -1e30f;
                    if (j0 + 1 > i0) s[nt][1] = -1e30f;
                    if (j0 > i0 + 8)     s[nt][2] = -1e30f;
                    if (j0 + 1 > i0 + 8) s[nt][3] = -1e30f;
                }
            }

            float alpha[2];
#pragma unroll
            for (int hrow = 0; hrow < 2; hrow++) {
                float mx = -1e30f;
#pragma unroll
                for (int nt = 0; nt < 8; nt++) {
                    mx = fmaxf(mx, s[nt][2 * hrow]);
                    mx = fmaxf(mx, s[nt][2 * hrow + 1]);
                }
                mx = fmaxf(mx, __shfl_xor_sync(0xffffffffu, mx, 1));
                mx = fmaxf(mx, __shfl_xor_sync(0xffffffffu, mx, 2));
                float mn = fmaxf(m_run[hrow], mx);
                alpha[hrow] = __expf(m_run[hrow] - mn);
                m_run[hrow] = mn;
                float rs = 0.f;
#pragma unroll
                for (int nt = 0; nt < 8; nt++) {
                    float p0 = __expf(s[nt][2 * hrow] - mn);
                    float p1 = __expf(s[nt][2 * hrow + 1] - mn);
                    s[nt][2 * hrow] = p0;
                    s[nt][2 * hrow + 1] = p1;
                    rs += p0 + p1;
                }
                rs += __shfl_xor_sync(0xffffffffu, rs, 1);
                rs += __shfl_xor_sync(0xffffffffu, rs, 2);
                l_run[hrow] = l_run[hrow] * alpha[hrow] + rs;
            }
#pragma unroll
            for (int nt = 0; nt < 8; nt++) {
                o[nt][0] *= alpha[0]; o[nt][1] *= alpha[0];
                o[nt][2] *= alpha[1]; o[nt][3] *= alpha[1];
            }

            const int src0 = (lane & ~3) | (qlane >> 1);
            const int src1 = src0 + 2;
#pragma unroll
            for (int ks = 0; ks < 8; ks++) {
                float v00 = __shfl_sync(0xffffffffu, s[ks][0], src0);
                float v01 = __shfl_sync(0xffffffffu, s[ks][1], src0);
                float v20 = __shfl_sync(0xffffffffu, s[ks][2], src0);
                float v21 = __shfl_sync(0xffffffffu, s[ks][3], src0);
                float v02 = __shfl_sync(0xffffffffu, s[ks][0], src1);
                float v03 = __shfl_sync(0xffffffffu, s[ks][1], src1);
                float v22 = __shfl_sync(0xffffffffu, s[ks][2], src1);
                float v23 = __shfl_sync(0xffffffffu, s[ks][3], src1);
                unsigned pa[4];
                pa[0] = f2tf((qlane & 1) ? v01 : v00);
                pa[1] = f2tf((qlane & 1) ? v21 : v20);
                pa[2] = f2tf((qlane & 1) ? v03 : v02);
                pa[3] = f2tf((qlane & 1) ? v23 : v22);
                int kr = ks * 8 + qlane;
#pragma unroll
                for (int nt = 0; nt < 8; nt++) {
                    unsigned vb[2];
                    vb[0] = Vs[kr * VPITCH + nt * 8 + grp];
                    vb[1] = Vs[(kr + 4) * VPITCH + nt * 8 + grp];
                    mma8(o[nt], pa, vb);
                }
            }
        }
    }

    // Epilogue: write fragment-PACKED tf32 directly (A operand of out-proj).
    float inv0 = 1.f / l_run[0];
    float inv1 = 1.f / l_run[1];
    const size_t rp = (size_t)(b * SEQ + q0) >> 7;   // 128-row panel index
#pragma unroll
    for (int nt = 0; nt < 8; nt++) {
        int c = hh * 64 + nt * 8 + 2 * qlane;
        int kp = c >> 5, kl = c & 31;
        size_t tb = (rp * 32 + kp) * 4096ull;
        int w0 = a_word(rloc, kl);
        outp[tb + w0]     = f2tf(o[nt][0] * inv0);
        outp[tb + w0 + 4] = f2tf(o[nt][1] * inv0);
        int w2 = a_word(rloc + 8, kl);
        outp[tb + w2]     = f2tf(o[nt][2] * inv1);
        outp[tb + w2 + 4] = f2tf(o[nt][3] * inv1);
    }
}

// ---------------------------------------------------------------------------
// Launch
// ---------------------------------------------------------------------------
extern "C" void kernel_launch(void* const* d_in, const int* in_sizes, int n_in,
                              void* d_out, int out_size) {
    const float* x     = (const float*)d_in[0];
    const int*   pos   = (const int*)d_in[1];
    const float* w_qkv = (const float*)d_in[2];
    const float* w_o   = (const float*)d_in[3];
    float* out = (float*)d_out;

    float *qkv = nullptr;
    unsigned *xp = nullptr, *wqp = nullptr, *wop = nullptr, *ap = nullptr;
    cudaGetSymbolAddress((void**)&qkv, g_qkv);
    cudaGetSymbolAddress((void**)&xp, g_xpack);
    cudaGetSymbolAddress((void**)&wqp, g_wqkv_pack);
    cudaGetSymbolAddress((void**)&wop, g_wo_pack);
    cudaGetSymbolAddress((void**)&ap, g_attn_pack);

    cudaFuncSetAttribute(gemm_packed,
                         cudaFuncAttributeMaxDynamicSharedMemorySize, GEMM_SMEM);
    cudaFuncSetAttribute(flash_tf32,
                         cudaFuncAttributeMaxDynamicSharedMemorySize, ATT_SMEM);

    // 0) Pack operands
    pack_a_kernel<<<(MTOT * DMODEL / 4 + 255) / 256, 256>>>(x, xp, MTOT, DMODEL);
    pack_b_kernel<<<(3 * DMODEL * DMODEL / 4 + 255) / 256, 256>>>(w_qkv, wqp,
                                                                  3 * DMODEL, DMODEL);
    pack_b_kernel<<<(DMODEL * DMODEL / 4 + 255) / 256, 256>>>(w_o, wop,
                                                              DMODEL, DMODEL);

    // 1) QKV projection
    gemm_packed<<<dim3(3 * DMODEL / 128, MTOT / 128), 256, GEMM_SMEM>>>(
        xp, wqp, qkv, MTOT, 3 * DMODEL, DMODEL);

    // 2) RoPE
    {
        int total = MTOT * NHEADS * (DK / 2);
        rope_kernel<<<(total + 255) / 256, 256>>>(qkv, pos);
    }

    // 3) Flash attention (writes packed A for the out-proj)
    flash_tf32<<<dim3(SEQ / 128, NHEADS, BATCH), 256, ATT_SMEM>>>(qkv, ap);

    // 4) Output projection
    gemm_packed<<<dim3(DMODEL / 128, MTOT / 128), 256, GEMM_SMEM>>>(
        ap, wop, out, MTOT, DMODEL, DMODEL);
}

// round 5
// speedup vs baseline: 6.7358x; 1.1663x over previous
#include <cuda_runtime.h>
#include <math.h>

#define BATCH 4
#define SEQ 2048
#define DMODEL 1024
#define NHEADS 16
#define DK 64
#define MTOT (BATCH * SEQ)   // 8192

// Scratch (module-load allocated)
__device__ unsigned g_xpack[(size_t)MTOT * DMODEL];          // x, tf32 A-frag32 packed
__device__ unsigned g_wqkv_pack[(size_t)3 * DMODEL * DMODEL];
__device__ unsigned g_wo_pack[(size_t)DMODEL * DMODEL];
__device__ unsigned g_qpack[(size_t)BATCH * NHEADS * 16 * 8192];  // Q A-frag64, rope+scaled
__device__ unsigned g_kpack[(size_t)BATCH * NHEADS * 32 * 4096];  // K B-frag64, rope
__device__ unsigned g_vpack[(size_t)BATCH * NHEADS * 32 * 4096];  // V^T B-frag64
__device__ unsigned g_attn_pack[(size_t)MTOT * DMODEL];      // attn out, A-frag32 packed

// ---------------------------------------------------------------------------
// tf32 / mma / cp.async helpers
// ---------------------------------------------------------------------------
__device__ __forceinline__ unsigned f2tf(float f) {
    unsigned r;
    asm("cvt.rna.tf32.f32 %0, %1;" : "=r"(r) : "f"(f));
    return r;
}

__device__ __forceinline__ void mma8(float* c, const unsigned* a, const unsigned* b) {
    asm volatile(
        "mma.sync.aligned.m16n8k8.row.col.f32.tf32.tf32.f32 "
        "{%0,%1,%2,%3},{%4,%5,%6,%7},{%8,%9},{%0,%1,%2,%3};"
        : "+f"(c[0]), "+f"(c[1]), "+f"(c[2]), "+f"(c[3])
        : "r"(a[0]), "r"(a[1]), "r"(a[2]), "r"(a[3]), "r"(b[0]), "r"(b[1]));
}

__device__ __forceinline__ void cp_async16(unsigned* smem_ptr, const unsigned* gptr) {
    unsigned sa = (unsigned)__cvta_generic_to_shared(smem_ptr);
    asm volatile("cp.async.cg.shared.global [%0], [%1], 16;" :: "r"(sa), "l"(gptr));
}
__device__ __forceinline__ void cp_commit() {
    asm volatile("cp.async.commit_group;");
}
__device__ __forceinline__ void cp_wait1() {
    asm volatile("cp.async.wait_group 1;");
}

// --- Fragment layouts, 32-k tiles (GEMM path, 128x32 tile = 4096 words) ---
__device__ __forceinline__ int a_word(int r, int kl) {
    return ((r >> 4) * 4 + (kl >> 3)) * 128 + ((r & 7) * 4 + (kl & 3)) * 4 +
           (((r >> 3) & 1) | (((kl >> 2) & 1) << 1));
}
__device__ __forceinline__ int b_word(int n, int kl) {
    return ((n >> 3) * 4 + (kl >> 3)) * 64 + ((n & 7) * 4 + (kl & 3)) * 2 +
           ((kl >> 2) & 1);
}
// --- Fragment layouts, 64-k tiles (flash path) ---
// A tile 128x64 = 8192 words; B tile 64x64 = 4096 words.
__device__ __forceinline__ int aw64(int r, int d) {
    return ((r >> 4) * 8 + (d >> 3)) * 128 + ((r & 7) * 4 + (d & 3)) * 4 +
           (((r >> 3) & 1) | (((d >> 2) & 1) << 1));
}
__device__ __forceinline__ int bw64(int n, int d) {
    return ((n >> 3) * 8 + (d >> 3)) * 64 + ((n & 7) * 4 + (d & 3)) * 2 +
           ((d >> 2) & 1);
}

// ---------------------------------------------------------------------------
// Pack kernels: row-major fp32 -> tf32 fragment-packed global (32-k tiles)
// ---------------------------------------------------------------------------
__global__ void pack_a_kernel(const float* __restrict__ src, unsigned* __restrict__ dst,
                              int ROWS, int K) {
    int idx = blockIdx.x * blockDim.x + threadIdx.x;
    int K4 = K >> 2;
    if (idx >= ROWS * K4) return;
    int rg = idx / K4;
    int c0 = (idx - rg * K4) << 2;
    float4 v = *(const float4*)&src[(size_t)rg * K + c0];
    int rp = rg >> 7, r = rg & 127, kp = c0 >> 5;
    size_t tile = ((size_t)rp * (K >> 5) + kp) * 4096;
    float vv[4] = {v.x, v.y, v.z, v.w};
#pragma unroll
    for (int j = 0; j < 4; j++) {
        int kl = (c0 & 31) + j;
        dst[tile + a_word(r, kl)] = f2tf(vv[j]);
    }
}

__global__ void pack_b_kernel(const float* __restrict__ src, unsigned* __restrict__ dst,
                              int ROWS, int K) {
    int idx = blockIdx.x * blockDim.x + threadIdx.x;
    int K4 = K >> 2;
    if (idx >= ROWS * K4) return;
    int ng = idx / K4;
    int c0 = (idx - ng * K4) << 2;
    float4 v = *(const float4*)&src[(size_t)ng * K + c0];
    int np = ng >> 7, n = ng & 127, kp = c0 >> 5;
    size_t tile = ((size_t)np * (K >> 5) + kp) * 4096;
    float vv[4] = {v.x, v.y, v.z, v.w};
#pragma unroll
    for (int j = 0; j < 4; j++) {
        int kl = (c0 & 31) + j;
        dst[tile + b_word(n, kl)] = f2tf(vv[j]);
    }
}

// ---------------------------------------------------------------------------
// Shared GEMM mainloop (128x128 tile, BK=32, 3-stage cp.async)
// ---------------------------------------------------------------------------
#define GEMM_SMEM (3 * 8192 * 4)

__device__ __forceinline__ void issue_stage(unsigned* smbase,
                                            const unsigned* __restrict__ Ap,
                                            const unsigned* __restrict__ Bp,
                                            int kt, int tid) {
    const unsigned* ga = Ap + (size_t)kt * 4096;
    const unsigned* gb = Bp + (size_t)kt * 4096;
#pragma unroll
    for (int i = 0; i < 4; i++) {
        int c = (tid + i * 256) * 4;
        cp_async16(smbase + c, ga + c);
        cp_async16(smbase + 4096 + c, gb + c);
    }
}

__device__ __forceinline__ void gemm_mainloop(
    const unsigned* __restrict__ Ap, const unsigned* __restrict__ Bp,
    unsigned* sm, int KT, int tid, int lane, int wm, int wn,
    float acc[2][8][4]) {
#pragma unroll
    for (int mt = 0; mt < 2; mt++)
#pragma unroll
        for (int nt = 0; nt < 8; nt++)
#pragma unroll
            for (int e = 0; e < 4; e++) acc[mt][nt][e] = 0.f;

    issue_stage(sm, Ap, Bp, 0, tid); cp_commit();
    issue_stage(sm + 8192, Ap, Bp, 1, tid); cp_commit();

    for (int kt = 0; kt < KT; kt++) {
        cp_wait1();
        __syncthreads();
        if (kt + 2 < KT)
            issue_stage(sm + ((kt + 2) % 3) * 8192, Ap, Bp, kt + 2, tid);
        cp_commit();

        const unsigned* As = sm + (kt % 3) * 8192;
        const unsigned* Bs = As + 4096;
#pragma unroll
        for (int ks = 0; ks < 4; ks++) {
            unsigned af[2][4], bf[8][2];
#pragma unroll
            for (int mt = 0; mt < 2; mt++)
                *(uint4*)af[mt] =
                    *(const uint4*)&As[((wm * 2 + mt) * 4 + ks) * 128 + lane * 4];
#pragma unroll
            for (int nt = 0; nt < 8; nt++)
                *(uint2*)bf[nt] =
                    *(const uint2*)&Bs[((wn * 8 + nt) * 4 + ks) * 64 + lane * 2];
#pragma unroll
            for (int mt = 0; mt < 2; mt++)
#pragma unroll
                for (int nt = 0; nt < 8; nt++)
                    mma8(acc[mt][nt], af[mt], bf[nt]);
        }
        __syncthreads();
    }
}

// ---------------------------------------------------------------------------
// Generic packed GEMM (used for out-proj): plain fp32 row-major C output.
// ---------------------------------------------------------------------------
__global__ __launch_bounds__(256, 2)
void gemm_packed(const unsigned* __restrict__ Apack, const unsigned* __restrict__ Bpack,
                 float* __restrict__ C, int M, int N, int K) {
    extern __shared__ unsigned sm[];
    const int tid = threadIdx.x;
    const int lane = tid & 31, wid = tid >> 5;
    const int wm = wid & 3, wn = wid >> 2;
    const int KT = K >> 5;

    const unsigned* Ap = Apack + (size_t)blockIdx.y * KT * 4096;
    const unsigned* Bp = Bpack + (size_t)blockIdx.x * KT * 4096;

    float acc[2][8][4];
    gemm_mainloop(Ap, Bp, sm, KT, tid, lane, wm, wn, acc);

    const int row0 = blockIdx.y * 128, col0 = blockIdx.x * 128;
#pragma unroll
    for (int mt = 0; mt < 2; mt++)
#pragma unroll
        for (int nt = 0; nt < 8; nt++) {
            int r = row0 + wm * 32 + mt * 16 + (lane >> 2);
            int cc = col0 + wn * 64 + nt * 8 + 2 * (lane & 3);
            *(float2*)&C[(size_t)r * N + cc] =
                make_float2(acc[mt][nt][0], acc[mt][nt][1]);
            *(float2*)&C[(size_t)(r + 8) * N + cc] =
                make_float2(acc[mt][nt][2], acc[mt][nt][3]);
        }
}

// ---------------------------------------------------------------------------
// QKV GEMM with fused RoPE + flash-layout packing epilogue.
// C columns: [0,1024)=Q (rope+scale, A-frag64), [1024,2048)=K (rope, B-frag64),
// [2048,3072)=V (V^T B-frag64).
// ---------------------------------------------------------------------------
__global__ __launch_bounds__(256, 2)
void gemm_qkv_rope(const unsigned* __restrict__ Apack, const unsigned* __restrict__ Bpack,
                   const int* __restrict__ pos,
                   unsigned* __restrict__ qp, unsigned* __restrict__ kpk,
                   unsigned* __restrict__ vp) {
    extern __shared__ unsigned sm[];
    const int tid = threadIdx.x;
    const int lane = tid & 31, wid = tid >> 5;
    const int wm = wid & 3, wn = wid >> 2;
    const int KT = DMODEL >> 5;   // 32

    const unsigned* Ap = Apack + (size_t)blockIdx.y * KT * 4096;
    const unsigned* Bp = Bpack + (size_t)blockIdx.x * KT * 4096;

    float acc[2][8][4];
    gemm_mainloop(Ap, Bp, sm, KT, tid, lane, wm, wn, acc);

    const int row0 = blockIdx.y * 128, col0 = blockIdx.x * 128;
#pragma unroll
    for (int mt = 0; mt < 2; mt++)
#pragma unroll
        for (int nt = 0; nt < 8; nt++) {
            int cg = col0 + wn * 64 + nt * 8 + 2 * (lane & 3);   // even
            int which = cg >> 10;
            int hh = (cg & 1023) >> 6;
            int d = cg & 63;                                      // even
#pragma unroll
            for (int half = 0; half < 2; half++) {
                int r = row0 + wm * 32 + mt * 16 + (lane >> 2) + half * 8;
                int b = r >> 11, s = r & 2047;
                float v0 = acc[mt][nt][2 * half];
                float v1 = acc[mt][nt][2 * half + 1];
                if (which < 2) {
                    float p = (float)pos[r];
                    // inv_freq = 10000^(-d/64) ; log2(10000)/64 = 0.2076205059...
                    float inv = exp2f((float)d * -0.20762050593046f);
                    float ang = p * inv, sn, cs;
                    sincosf(ang, &sn, &cs);
                    float r0 = v0 * cs - v1 * sn;
                    float r1 = v0 * sn + v1 * cs;
                    if (which == 0) {
                        size_t base = ((size_t)(b * NHEADS + hh) * 16 + (s >> 7)) * 8192;
                        qp[base + aw64(s & 127, d)]     = f2tf(r0 * 0.125f);
                        qp[base + aw64(s & 127, d + 1)] = f2tf(r1 * 0.125f);
                    } else {
                        size_t base = ((size_t)(b * NHEADS + hh) * 32 + (s >> 6)) * 4096;
                        kpk[base + bw64(s & 63, d)]     = f2tf(r0);
                        kpk[base + bw64(s & 63, d + 1)] = f2tf(r1);
                    }
                } else {
                    size_t base = ((size_t)(b * NHEADS + hh) * 32 + (s >> 6)) * 4096;
                    vp[base + bw64(d,     s & 63)] = f2tf(v0);
                    vp[base + bw64(d + 1, s & 63)] = f2tf(v1);
                }
            }
        }
}

// ---------------------------------------------------------------------------
// Causal flash attention on packed tf32 operands.
// 256 threads (8 warps = 8 row-groups of 16), BQ=128, BKEY=64.
// Q: cp.async once (32KB). K/V: 2-stage cp.async pipeline (32KB/stage).
// ---------------------------------------------------------------------------
#define FL_SMEM ((8192 + 2 * 8192) * 4)   // 96 KB

__global__ __launch_bounds__(256, 2)
void flash_packed(const unsigned* __restrict__ Qp, const unsigned* __restrict__ Kp,
                  const unsigned* __restrict__ Vp, unsigned* __restrict__ outp) {
    extern __shared__ unsigned sm[];
    unsigned* Qs = sm;            // 8192 words
    unsigned* St = sm + 8192;     // 2 x (K 4096 | V 4096)

    const int qb = gridDim.x - 1 - blockIdx.x;   // heavy tiles first
    const int hh = blockIdx.y;
    const int b  = blockIdx.z;
    const int q0 = qb * 128;
    const int tid = threadIdx.x;
    const int lane = tid & 31, w = tid >> 5;
    const int qlane = lane & 3, grp = lane >> 2;

    const unsigned* qg = Qp + ((size_t)(b * NHEADS + hh) * 16 + qb) * 8192;
    const unsigned* kg = Kp + ((size_t)(b * NHEADS + hh) * 32) * 4096;
    const unsigned* vg = Vp + ((size_t)(b * NHEADS + hh) * 32) * 4096;

    const int ktiles = qb * 2 + 2;

    // group 0: Q tile + KV tile 0
#pragma unroll
    for (int i = 0; i < 8; i++) {
        int c = (tid + i * 256) * 4;
        cp_async16(Qs + c, qg + c);
    }
#pragma unroll
    for (int i = 0; i < 4; i++) {
        int c = (tid + i * 256) * 4;
        cp_async16(St + c, kg + c);
        cp_async16(St + 4096 + c, vg + c);
    }
    cp_commit();
    // group 1: KV tile 1
#pragma unroll
    for (int i = 0; i < 4; i++) {
        int c = (tid + i * 256) * 4;
        cp_async16(St + 8192 + c, kg + 4096 + c);
        cp_async16(St + 8192 + 4096 + c, vg + 4096 + c);
    }
    cp_commit();

    float o[8][4];
#pragma unroll
    for (int nt = 0; nt < 8; nt++)
#pragma unroll
        for (int e = 0; e < 4; e++) o[nt][e] = 0.f;
    float m_run[2] = {-1e30f, -1e30f};
    float l_run[2] = {0.f, 0.f};

    const int rloc = w * 16 + grp;

    for (int kt = 0; kt < ktiles; kt++) {
        const int k0 = kt * 64;
        cp_wait1();
        __syncthreads();
        const unsigned* Ks = St + (kt & 1) * 8192;
        const unsigned* Vs = Ks + 4096;

        if (k0 <= q0 + w * 16 + 15) {
            // ---- S = Q K^T ----
            float s[8][4];
#pragma unroll
            for (int nt = 0; nt < 8; nt++)
#pragma unroll
                for (int e = 0; e < 4; e++) s[nt][e] = 0.f;

#pragma unroll
            for (int ks = 0; ks < 8; ks++) {
                unsigned qa[4];
                *(uint4*)qa = *(const uint4*)&Qs[(w * 8 + ks) * 128 + lane * 4];
#pragma unroll
                for (int nt = 0; nt < 8; nt++) {
                    unsigned bfr[2];
                    *(uint2*)bfr = *(const uint2*)&Ks[(nt * 8 + ks) * 64 + lane * 2];
                    mma8(s[nt], qa, bfr);
                }
            }

            // ---- causal mask (diagonal-overlapping tiles) ----
            if (k0 + 63 > q0 + w * 16) {
                int i0 = q0 + rloc;
#pragma unroll
                for (int nt = 0; nt < 8; nt++) {
                    int j0 = k0 + nt * 8 + 2 * qlane;
                    if (j0 > i0)         s[nt][0] = -1e30f;
                    if (j0 + 1 > i0)     s[nt][1] = -1e30f;
                    if (j0 > i0 + 8)     s[nt][2] = -1e30f;
                    if (j0 + 1 > i0 + 8) s[nt][3] = -1e30f;
                }
            }

            // ---- online softmax ----
            float alpha[2];
#pragma unroll
            for (int hrow = 0; hrow < 2; hrow++) {
                float mx = -1e30f;
#pragma unroll
                for (int nt = 0; nt < 8; nt++) {
                    mx = fmaxf(mx, s[nt][2 * hrow]);
                    mx = fmaxf(mx, s[nt][2 * hrow + 1]);
                }
                mx = fmaxf(mx, __shfl_xor_sync(0xffffffffu, mx, 1));
                mx = fmaxf(mx, __shfl_xor_sync(0xffffffffu, mx, 2));
                float mn = fmaxf(m_run[hrow], mx);
                alpha[hrow] = __expf(m_run[hrow] - mn);
                m_run[hrow] = mn;
                float rs = 0.f;
#pragma unroll
                for (int nt = 0; nt < 8; nt++) {
                    float p0 = __expf(s[nt][2 * hrow] - mn);
                    float p1 = __expf(s[nt][2 * hrow + 1] - mn);
                    s[nt][2 * hrow] = p0;
                    s[nt][2 * hrow + 1] = p1;
                    rs += p0 + p1;
                }
                rs += __shfl_xor_sync(0xffffffffu, rs, 1);
                rs += __shfl_xor_sync(0xffffffffu, rs, 2);
                l_run[hrow] = l_run[hrow] * alpha[hrow] + rs;
            }
#pragma unroll
            for (int nt = 0; nt < 8; nt++) {
                o[nt][0] *= alpha[0]; o[nt][1] *= alpha[0];
                o[nt][2] *= alpha[1]; o[nt][3] *= alpha[1];
            }

            // ---- O += P V (P C-frags -> A-frags via quad shuffles) ----
            const int src0 = (lane & ~3) | (qlane >> 1);
            const int src1 = src0 + 2;
#pragma unroll
            for (int ks = 0; ks < 8; ks++) {
                float v00 = __shfl_sync(0xffffffffu, s[ks][0], src0);
                float v01 = __shfl_sync(0xffffffffu, s[ks][1], src0);
                float v20 = __shfl_sync(0xffffffffu, s[ks][2], src0);
                float v21 = __shfl_sync(0xffffffffu, s[ks][3], src0);
                float v02 = __shfl_sync(0xffffffffu, s[ks][0], src1);
                float v03 = __shfl_sync(0xffffffffu, s[ks][1], src1);
                float v22 = __shfl_sync(0xffffffffu, s[ks][2], src1);
                float v23 = __shfl_sync(0xffffffffu, s[ks][3], src1);
                unsigned pa[4];
                pa[0] = f2tf((qlane & 1) ? v01 : v00);
                pa[1] = f2tf((qlane & 1) ? v21 : v20);
                pa[2] = f2tf((qlane & 1) ? v03 : v02);
                pa[3] = f2tf((qlane & 1) ? v23 : v22);
#pragma unroll
                for (int nt = 0; nt < 8; nt++) {
                    unsigned vb[2];
                    *(uint2*)vb = *(const uint2*)&Vs[(nt * 8 + ks) * 64 + lane * 2];
                    mma8(o[nt], pa, vb);
                }
            }
        }

        __syncthreads();
        if (kt + 2 < ktiles) {
            const unsigned* kgn = kg + (size_t)(kt + 2) * 4096;
            const unsigned* vgn = vg + (size_t)(kt + 2) * 4096;
            unsigned* dst = St + (kt & 1) * 8192;
#pragma unroll
            for (int i = 0; i < 4; i++) {
                int c = (tid + i * 256) * 4;
                cp_async16(dst + c, kgn + c);
                cp_async16(dst + 4096 + c, vgn + c);
            }
        }
        cp_commit();
    }

    // Epilogue: write fragment-PACKED tf32 (A operand of out-proj, 32-k tiles).
    float inv0 = 1.f / l_run[0];
    float inv1 = 1.f / l_run[1];
    const size_t rp = (size_t)(b * SEQ + q0) >> 7;
#pragma unroll
    for (int nt = 0; nt < 8; nt++) {
        int c = hh * 64 + nt * 8 + 2 * qlane;
        int kp = c >> 5, kl = c & 31;
        size_t tb = (rp * 32 + kp) * 4096ull;
        int w0 = a_word(rloc, kl);
        outp[tb + w0]     = f2tf(o[nt][0] * inv0);
        outp[tb + w0 + 4] = f2tf(o[nt][1] * inv0);
        int w2 = a_word(rloc + 8, kl);
        outp[tb + w2]     = f2tf(o[nt][2] * inv1);
        outp[tb + w2 + 4] = f2tf(o[nt][3] * inv1);
    }
}

// ---------------------------------------------------------------------------
// Launch
// ---------------------------------------------------------------------------
extern "C" void kernel_launch(void* const* d_in, const int* in_sizes, int n_in,
                              void* d_out, int out_size) {
    const float* x     = (const float*)d_in[0];
    const int*   pos   = (const int*)d_in[1];
    const float* w_qkv = (const float*)d_in[2];
    const float* w_o   = (const float*)d_in[3];
    float* out = (float*)d_out;

    unsigned *xp = nullptr, *wqp = nullptr, *wop = nullptr, *ap = nullptr;
    unsigned *qp = nullptr, *kp = nullptr, *vp = nullptr;
    cudaGetSymbolAddress((void**)&xp, g_xpack);
    cudaGetSymbolAddress((void**)&wqp, g_wqkv_pack);
    cudaGetSymbolAddress((void**)&wop, g_wo_pack);
    cudaGetSymbolAddress((void**)&ap, g_attn_pack);
    cudaGetSymbolAddress((void**)&qp, g_qpack);
    cudaGetSymbolAddress((void**)&kp, g_kpack);
    cudaGetSymbolAddress((void**)&vp, g_vpack);

    cudaFuncSetAttribute(gemm_packed,
                         cudaFuncAttributeMaxDynamicSharedMemorySize, GEMM_SMEM);
    cudaFuncSetAttribute(gemm_qkv_rope,
                         cudaFuncAttributeMaxDynamicSharedMemorySize, GEMM_SMEM);
    cudaFuncSetAttribute(flash_packed,
                         cudaFuncAttributeMaxDynamicSharedMemorySize, FL_SMEM);

    // 0) Pack operands
    pack_a_kernel<<<(MTOT * DMODEL / 4 + 255) / 256, 256>>>(x, xp, MTOT, DMODEL);
    pack_b_kernel<<<(3 * DMODEL * DMODEL / 4 + 255) / 256, 256>>>(w_qkv, wqp,
                                                                  3 * DMODEL, DMODEL);
    pack_b_kernel<<<(DMODEL * DMODEL / 4 + 255) / 256, 256>>>(w_o, wop,
                                                              DMODEL, DMODEL);

    // 1) QKV projection + fused RoPE + flash-layout packing
    gemm_qkv_rope<<<dim3(3 * DMODEL / 128, MTOT / 128), 256, GEMM_SMEM>>>(
        xp, wqp, pos, qp, kp, vp);

    // 2) Flash attention on packed tf32 (writes packed A for the out-proj)
    flash_packed<<<dim3(SEQ / 128, NHEADS, BATCH), 256, FL_SMEM>>>(qp, kp, vp, ap);

    // 3) Output projection
    gemm_packed<<<dim3(DMODEL / 128, MTOT / 128), 256, GEMM_SMEM>>>(
        ap, wop, out, MTOT, DMODEL, DMODEL);
}